// round 2
// baseline (speedup 1.0000x reference)
#include <cuda_runtime.h>
#include <cuda_bf16.h>
#include <math.h>

#define B 8
#define DIM 8192
#define HEAD_DIM 128
#define N_KV 8
#define N_REP 8
#define NH 64          // total q heads
#define KV 4096
#define E 8
#define FD 2048
#define FE 1024
#define QKV_N 10240

// ---------------- scratch (device globals; no allocation allowed) ----------------
__device__ float g_an[B * DIM];
__device__ float g_qkv[B * QKV_N];
__device__ float g_q[B * NH * HEAD_DIM];
__device__ float g_knew[B * N_KV * HEAD_DIM];
__device__ float g_vnew[B * N_KV * HEAD_DIM];
__device__ float g_scores[(size_t)B * NH * KV];
__device__ float g_attn[B * DIM];
__device__ float g_h[B * DIM];
__device__ float g_fin[B * DIM];
__device__ float g_t1[B * FD];
__device__ float g_t3[B * FD];
__device__ float g_g[B * FD];
__device__ float g_glog[B * E];
__device__ float g_wexp[B * E];
__device__ float g_h1[B * E * FE];
__device__ float g_h3[B * E * FE];
__device__ float g_ge[B * E * FE];

// ---------------- rmsnorm ----------------
__global__ void rmsnorm_kernel(const float* __restrict__ x, const float* __restrict__ w,
                               float* __restrict__ out) {
    int b = blockIdx.x;
    const float* xb = x + (size_t)b * DIM;
    float* ob = out + (size_t)b * DIM;
    float ss = 0.f;
    for (int i = threadIdx.x; i < DIM; i += blockDim.x) {
        float v = xb[i];
        ss += v * v;
    }
    // block reduce
    __shared__ float red[32];
    for (int off = 16; off > 0; off >>= 1) ss += __shfl_xor_sync(0xffffffffu, ss, off);
    int lane = threadIdx.x & 31, warp = threadIdx.x >> 5;
    if (lane == 0) red[warp] = ss;
    __syncthreads();
    if (warp == 0) {
        float v = (lane < (int)(blockDim.x >> 5)) ? red[lane] : 0.f;
        for (int off = 16; off > 0; off >>= 1) v += __shfl_xor_sync(0xffffffffu, v, off);
        if (lane == 0) red[0] = v;
    }
    __syncthreads();
    float scale = rsqrtf(red[0] / (float)DIM + 1e-5f);
    for (int i = threadIdx.x; i < DIM; i += blockDim.x)
        ob[i] = xb[i] * scale * w[i];
}

// ---------------- column-major GEMV (x[B,K] @ W[K,N]) with k-splits + atomicAdd ----------------
__global__ void gemv_cm_kernel(const float* __restrict__ x, const float* __restrict__ W,
                               float* __restrict__ out, int K, int N) {
    int n = blockIdx.x * blockDim.x + threadIdx.x;
    int kchunk = K / gridDim.y;
    int k0 = blockIdx.y * kchunk;
    __shared__ float xs[B][64];
    float acc[B];
#pragma unroll
    for (int b = 0; b < B; ++b) acc[b] = 0.f;
    for (int kb = k0; kb < k0 + kchunk; kb += 64) {
        __syncthreads();
        for (int i = threadIdx.x; i < B * 64; i += blockDim.x) {
            int b = i >> 6, kk = i & 63;
            xs[b][kk] = x[(size_t)b * K + kb + kk];
        }
        __syncthreads();
        const float* Wp = W + (size_t)kb * N + n;
#pragma unroll 8
        for (int kk = 0; kk < 64; ++kk) {
            float w = Wp[(size_t)kk * N];
#pragma unroll
            for (int b = 0; b < B; ++b) acc[b] += xs[b][kk] * w;
        }
    }
#pragma unroll
    for (int b = 0; b < B; ++b) atomicAdd(&out[(size_t)b * N + n], acc[b]);
}

// ---------------- row-major GEMV: out[b,n] = dot(x[b,:], W[n,:]) + add[b,n] ----------------
__global__ void gemv_rm_kernel(const float* __restrict__ x, const float* __restrict__ W,
                               float* __restrict__ out, int N, int K,
                               const float* __restrict__ addsrc) {
    int warp = threadIdx.x >> 5, lane = threadIdx.x & 31;
    int n = blockIdx.x * (blockDim.x >> 5) + warp;
    if (n >= N) return;
    const float4* Wrow = (const float4*)(W + (size_t)n * K);
    const float4* x4 = (const float4*)x;
    int K4 = K >> 2;
    float acc[B];
#pragma unroll
    for (int b = 0; b < B; ++b) acc[b] = 0.f;
    for (int i = lane; i < K4; i += 32) {
        float4 w = Wrow[i];
#pragma unroll
        for (int b = 0; b < B; ++b) {
            float4 xv = x4[(size_t)b * K4 + i];
            acc[b] += w.x * xv.x + w.y * xv.y + w.z * xv.z + w.w * xv.w;
        }
    }
#pragma unroll
    for (int b = 0; b < B; ++b)
        for (int off = 16; off > 0; off >>= 1)
            acc[b] += __shfl_xor_sync(0xffffffffu, acc[b], off);
    if (lane == 0) {
#pragma unroll
        for (int b = 0; b < B; ++b) {
            float r = acc[b];
            if (addsrc) r += addsrc[(size_t)b * N + n];
            out[(size_t)b * N + n] = r;
        }
    }
}

// ---------------- rope + split qkv ----------------
__global__ void rope_split_kernel(const float* __restrict__ qkv,
                                  const float* __restrict__ fc, const float* __restrict__ fs,
                                  float* __restrict__ q, float* __restrict__ knew,
                                  float* __restrict__ vnew) {
    int b = blockIdx.x;
    const float* qb = qkv + (size_t)b * QKV_N;
    // q: 64 heads x 64 pairs
    for (int i = threadIdx.x; i < NH * 64; i += blockDim.x) {
        int h = i >> 6, pi = i & 63;
        int g = h >> 3, r = h & 7;
        const float* base = qb + g * 1280 + r * 128;
        float re = base[2 * pi], im = base[2 * pi + 1];
        float c = fc[pi], s = fs[pi];
        float* qo = q + ((size_t)b * NH + h) * HEAD_DIM;
        qo[2 * pi] = re * c - im * s;
        qo[2 * pi + 1] = re * s + im * c;
    }
    // k: 8 kv heads x 64 pairs
    for (int i = threadIdx.x; i < N_KV * 64; i += blockDim.x) {
        int g = i >> 6, pi = i & 63;
        const float* base = qb + g * 1280 + 1024;
        float re = base[2 * pi], im = base[2 * pi + 1];
        float c = fc[pi], s = fs[pi];
        float* ko = knew + ((size_t)b * N_KV + g) * HEAD_DIM;
        ko[2 * pi] = re * c - im * s;
        ko[2 * pi + 1] = re * s + im * c;
    }
    // v copy
    for (int i = threadIdx.x; i < N_KV * HEAD_DIM; i += blockDim.x) {
        int g = i >> 7, d = i & 127;
        vnew[((size_t)b * N_KV + g) * HEAD_DIM + i % HEAD_DIM] =
            qb[g * 1280 + 1152 + d];
    }
}

// ---------------- scores ----------------
__global__ void scores_kernel(const float* __restrict__ q, const float* __restrict__ cache_k,
                              const float* __restrict__ knew, const float* __restrict__ mask,
                              const int* __restrict__ sp_ptr, float* __restrict__ scores) {
    int b = blockIdx.z, g = blockIdx.y, j0 = blockIdx.x * 32;
    int sp = *sp_ptr;
    __shared__ float ks[32][129];
    __shared__ float qs[8][129];
    for (int i = threadIdx.x; i < 8 * 128; i += blockDim.x) {
        int r = i >> 7, d = i & 127;
        qs[r][d] = q[((size_t)b * NH + g * 8 + r) * HEAD_DIM + d];
    }
    for (int i = threadIdx.x; i < 32 * 128; i += blockDim.x) {
        int jl = i >> 7, d = i & 127;
        int j = j0 + jl;
        float v = (j == sp) ? knew[((size_t)b * N_KV + g) * HEAD_DIM + d]
                            : cache_k[(((size_t)b * KV + j) * N_KV + g) * HEAD_DIM + d];
        ks[jl][d] = v;
    }
    __syncthreads();
    int jl = threadIdx.x >> 3, r = threadIdx.x & 7;
    float s = 0.f;
#pragma unroll 8
    for (int d = 0; d < HEAD_DIM; ++d) s += ks[jl][d] * qs[r][d];
    const float scale = 0.08838834764831845f;
    int j = j0 + jl;
    scores[((size_t)b * NH + g * 8 + r) * KV + j] = s * scale + mask[j];
}

// ---------------- softmax over KV ----------------
__global__ void softmax_kernel(float* __restrict__ scores) {
    size_t row = blockIdx.x;
    float* p = scores + row * KV;
    __shared__ float red[32];
    int lane = threadIdx.x & 31, warp = threadIdx.x >> 5;
    float m = -1e30f;
    for (int i = threadIdx.x; i < KV; i += blockDim.x) m = fmaxf(m, p[i]);
    for (int off = 16; off > 0; off >>= 1) m = fmaxf(m, __shfl_xor_sync(0xffffffffu, m, off));
    if (lane == 0) red[warp] = m;
    __syncthreads();
    if (warp == 0) {
        float v = (lane < (int)(blockDim.x >> 5)) ? red[lane] : -1e30f;
        for (int off = 16; off > 0; off >>= 1) v = fmaxf(v, __shfl_xor_sync(0xffffffffu, v, off));
        if (lane == 0) red[0] = v;
    }
    __syncthreads();
    m = red[0];
    __syncthreads();
    float sum = 0.f;
    for (int i = threadIdx.x; i < KV; i += blockDim.x) {
        float e = expf(p[i] - m);
        p[i] = e;
        sum += e;
    }
    for (int off = 16; off > 0; off >>= 1) sum += __shfl_xor_sync(0xffffffffu, sum, off);
    if (lane == 0) red[warp] = sum;
    __syncthreads();
    if (warp == 0) {
        float v = (lane < (int)(blockDim.x >> 5)) ? red[lane] : 0.f;
        for (int off = 16; off > 0; off >>= 1) v += __shfl_xor_sync(0xffffffffu, v, off);
        if (lane == 0) red[0] = v;
    }
    __syncthreads();
    float inv = 1.f / red[0];
    for (int i = threadIdx.x; i < KV; i += blockDim.x) p[i] *= inv;
}

// ---------------- P @ V (8 KV splits, atomicAdd into zeroed attn_out) ----------------
__global__ void pv_kernel(const float* __restrict__ p, const float* __restrict__ cache_v,
                          const float* __restrict__ vnew, const int* __restrict__ sp_ptr,
                          float* __restrict__ attn_out) {
    int b = blockIdx.z, g = blockIdx.y, split = blockIdx.x;
    int sp = *sp_ptr;
    int d = threadIdx.x & 127, half = threadIdx.x >> 7;  // half in {0,1}
    float acc[4] = {0.f, 0.f, 0.f, 0.f};
    __shared__ float ps[8][64];
    int jstart = split * 512;
    for (int jb = jstart; jb < jstart + 512; jb += 64) {
        __syncthreads();
        for (int i = threadIdx.x; i < 8 * 64; i += blockDim.x) {
            int r = i >> 6, jl = i & 63;
            ps[r][jl] = p[((size_t)b * NH + g * 8 + r) * KV + jb + jl];
        }
        __syncthreads();
        for (int jl = 0; jl < 64; ++jl) {
            int j = jb + jl;
            float v = (j == sp) ? vnew[((size_t)b * N_KV + g) * HEAD_DIM + d]
                                : cache_v[(((size_t)b * KV + j) * N_KV + g) * HEAD_DIM + d];
#pragma unroll
            for (int rr = 0; rr < 4; ++rr) acc[rr] += ps[half * 4 + rr][jl] * v;
        }
    }
#pragma unroll
    for (int rr = 0; rr < 4; ++rr)
        atomicAdd(&attn_out[((size_t)b * NH + g * 8 + half * 4 + rr) * HEAD_DIM + d], acc[rr]);
}

// ---------------- gelu(t1) * t3 ----------------
__global__ void gelumul_kernel(const float* __restrict__ t1, const float* __restrict__ t3,
                               float* __restrict__ g, int n) {
    int i = blockIdx.x * blockDim.x + threadIdx.x;
    if (i < n) {
        float x = t1[i];
        g[i] = 0.5f * x * (1.f + erff(x * 0.7071067811865476f)) * t3[i];
    }
}

// ---------------- gate softmax + top-2 weights ----------------
__global__ void gate_topk_kernel(const float* __restrict__ logits, float* __restrict__ wexp) {
    int b = threadIdx.x;
    if (b >= B) return;
    float l[E];
    float m = -1e30f;
#pragma unroll
    for (int e = 0; e < E; ++e) { l[e] = logits[b * E + e]; m = fmaxf(m, l[e]); }
    float sum = 0.f;
#pragma unroll
    for (int e = 0; e < E; ++e) { l[e] = expf(l[e] - m); sum += l[e]; }
#pragma unroll
    for (int e = 0; e < E; ++e) l[e] /= sum;
    // top-1 (first max), top-2 (first max excluding top-1)
    int i1 = 0;
#pragma unroll
    for (int e = 1; e < E; ++e) if (l[e] > l[i1]) i1 = e;
    int i2 = (i1 == 0) ? 1 : 0;
#pragma unroll
    for (int e = 0; e < E; ++e) if (e != i1 && l[e] > l[i2]) i2 = e;
#pragma unroll
    for (int e = 0; e < E; ++e)
        wexp[b * E + e] = (e == i1) ? l[i1] : (e == i2) ? l[i2] : 0.f;
}

// ---------------- MoE second GEMM: out[b,n] += wexp[b,e] * dot(ge[b,e,:], w2[e,n,:]) ----------------
__global__ void moe_second_kernel(const float* __restrict__ ge, const float* __restrict__ w2,
                                  const float* __restrict__ wexp, float* __restrict__ out) {
    int warp = threadIdx.x >> 5, lane = threadIdx.x & 31;
    int n = blockIdx.x * (blockDim.x >> 5) + warp;
    int e = blockIdx.y;
    // skip expert if no token selected it
    float wsel = (lane < B) ? wexp[lane * E + e] : 0.f;
    if (__ballot_sync(0xffffffffu, wsel != 0.f) == 0u) return;
    const float4* Wrow = (const float4*)(w2 + ((size_t)e * DIM + n) * FE);
    const float4* x4 = (const float4*)ge;
    float acc[B];
#pragma unroll
    for (int b = 0; b < B; ++b) acc[b] = 0.f;
    for (int i = lane; i < FE / 4; i += 32) {
        float4 w = Wrow[i];
#pragma unroll
        for (int b = 0; b < B; ++b) {
            float4 xv = x4[((size_t)b * E + e) * (FE / 4) + i];
            acc[b] += w.x * xv.x + w.y * xv.y + w.z * xv.z + w.w * xv.w;
        }
    }
#pragma unroll
    for (int b = 0; b < B; ++b)
        for (int off = 16; off > 0; off >>= 1)
            acc[b] += __shfl_xor_sync(0xffffffffu, acc[b], off);
    if (lane == 0) {
#pragma unroll
        for (int b = 0; b < B; ++b) {
            float c = wexp[b * E + e];
            if (c != 0.f) atomicAdd(&out[(size_t)b * DIM + n], c * acc[b]);
        }
    }
}

// ---------------- launch ----------------
extern "C" void kernel_launch(void* const* d_in, const int* in_sizes, int n_in,
                              void* d_out, int out_size) {
    const float* x        = (const float*)d_in[0];
    const float* mask     = (const float*)d_in[1];
    const float* fcos     = (const float*)d_in[2];
    const float* fsin     = (const float*)d_in[3];
    const float* cache_k  = (const float*)d_in[4];
    const float* cache_v  = (const float*)d_in[5];
    const float* wqkv     = (const float*)d_in[6];
    const float* wo       = (const float*)d_in[7];
    const float* attn_nw  = (const float*)d_in[8];
    const float* ffn_nw   = (const float*)d_in[9];
    const float* ffn_w1   = (const float*)d_in[10];
    const float* ffn_w2   = (const float*)d_in[11];
    const float* ffn_w3   = (const float*)d_in[12];
    const float* gate_w   = (const float*)d_in[13];
    const float* moe_w1   = (const float*)d_in[14];
    const float* moe_w2   = (const float*)d_in[15];
    const float* moe_w3   = (const float*)d_in[16];
    const int*   sp       = (const int*)d_in[17];
    float* out            = (float*)d_out;

    float *an, *qkv, *q, *knew, *vnew, *scores, *attn, *h, *fin, *t1, *t3, *gg;
    float *glog, *wexp, *h1, *h3, *ge;
    cudaGetSymbolAddress((void**)&an, g_an);
    cudaGetSymbolAddress((void**)&qkv, g_qkv);
    cudaGetSymbolAddress((void**)&q, g_q);
    cudaGetSymbolAddress((void**)&knew, g_knew);
    cudaGetSymbolAddress((void**)&vnew, g_vnew);
    cudaGetSymbolAddress((void**)&scores, g_scores);
    cudaGetSymbolAddress((void**)&attn, g_attn);
    cudaGetSymbolAddress((void**)&h, g_h);
    cudaGetSymbolAddress((void**)&fin, g_fin);
    cudaGetSymbolAddress((void**)&t1, g_t1);
    cudaGetSymbolAddress((void**)&t3, g_t3);
    cudaGetSymbolAddress((void**)&gg, g_g);
    cudaGetSymbolAddress((void**)&glog, g_glog);
    cudaGetSymbolAddress((void**)&wexp, g_wexp);
    cudaGetSymbolAddress((void**)&h1, g_h1);
    cudaGetSymbolAddress((void**)&h3, g_h3);
    cudaGetSymbolAddress((void**)&ge, g_ge);

    cudaMemsetAsync(qkv, 0, sizeof(float) * B * QKV_N);
    cudaMemsetAsync(attn, 0, sizeof(float) * B * DIM);

    // 1. attention pre-norm
    rmsnorm_kernel<<<B, 256>>>(x, attn_nw, an);
    // 2. qkv = an @ wqkv   (column-major, k-split)
    gemv_cm_kernel<<<dim3(QKV_N / 128, 8), 128>>>(an, wqkv, qkv, DIM, QKV_N);
    // 3. rope + split
    rope_split_kernel<<<B, 512>>>(qkv, fcos, fsin, q, knew, vnew);
    // 4. scores
    scores_kernel<<<dim3(KV / 32, N_KV, B), 256>>>(q, cache_k, knew, mask, sp, scores);
    // 5. softmax
    softmax_kernel<<<B * NH, 256>>>(scores);
    // 6. P @ V
    pv_kernel<<<dim3(8, N_KV, B), 256>>>(scores, cache_v, vnew, sp, attn);
    // 7. h = x + attn @ wo.T
    gemv_rm_kernel<<<DIM / 8, 256>>>(attn, wo, h, DIM, DIM, x);
    // 8. ffn pre-norm
    rmsnorm_kernel<<<B, 256>>>(h, ffn_nw, fin);
    // 9. dense FFN
    gemv_rm_kernel<<<FD / 8, 256>>>(fin, ffn_w1, t1, FD, DIM, nullptr);
    gemv_rm_kernel<<<FD / 8, 256>>>(fin, ffn_w3, t3, FD, DIM, nullptr);
    gelumul_kernel<<<(B * FD) / 256, 256>>>(t1, t3, gg, B * FD);
    gemv_rm_kernel<<<DIM / 8, 256>>>(gg, ffn_w2, out, DIM, FD, h);  // out = h + ff
    // 10. gating
    gemv_rm_kernel<<<1, 256>>>(fin, gate_w, glog, E, DIM, nullptr);
    gate_topk_kernel<<<1, 32>>>(glog, wexp);
    // 11. MoE up-projections (all experts: moe_w1/w3 are contiguous (E*FE, DIM))
    gemv_rm_kernel<<<(E * FE) / 8, 256>>>(fin, moe_w1, h1, E * FE, DIM, nullptr);
    gemv_rm_kernel<<<(E * FE) / 8, 256>>>(fin, moe_w3, h3, E * FE, DIM, nullptr);
    gelumul_kernel<<<(B * E * FE) / 256, 256>>>(h1, h3, ge, B * E * FE);
    // 12. MoE down-projection, weighted accumulate into out
    moe_second_kernel<<<dim3(DIM / 8, E), 256>>>(ge, moe_w2, wexp, out);
}

// round 3
// speedup vs baseline: 1.8469x; 1.8469x over previous
#include <cuda_runtime.h>
#include <cuda_bf16.h>
#include <math.h>

#define B 8
#define DIM 8192
#define HEAD_DIM 128
#define N_KV 8
#define N_REP 8
#define NH 64
#define KV 4096
#define E 8
#define FD 2048
#define FE 1024
#define QKV_N 10240

// ---------------- scratch ----------------
__device__ float g_an[B * DIM];
__device__ float g_qkv[B * QKV_N];
__device__ float g_q[B * NH * HEAD_DIM];
__device__ float g_knew[B * N_KV * HEAD_DIM];
__device__ float g_vnew[B * N_KV * HEAD_DIM];
__device__ float g_scores[(size_t)B * NH * KV];
__device__ float g_attn[B * DIM];
__device__ float g_h[B * DIM];
__device__ float g_fin[B * DIM];
__device__ float g_t1[B * FD];
__device__ float g_t3[B * FD];
__device__ float g_g[B * FD];
__device__ float g_glog[B * E];
__device__ float g_wexp[B * E];
__device__ float g_h1[B * E * FE];
__device__ float g_h3[B * E * FE];
__device__ float g_ge[B * E * FE];

// ---------------- rmsnorm ----------------
__global__ void rmsnorm_kernel(const float* __restrict__ x, const float* __restrict__ w,
                               float* __restrict__ out) {
    int b = blockIdx.x;
    const float* xb = x + (size_t)b * DIM;
    float* ob = out + (size_t)b * DIM;
    float ss = 0.f;
    for (int i = threadIdx.x; i < DIM; i += blockDim.x) {
        float v = xb[i];
        ss += v * v;
    }
    __shared__ float red[32];
    for (int off = 16; off > 0; off >>= 1) ss += __shfl_xor_sync(0xffffffffu, ss, off);
    int lane = threadIdx.x & 31, warp = threadIdx.x >> 5;
    if (lane == 0) red[warp] = ss;
    __syncthreads();
    if (warp == 0) {
        float v = (lane < (int)(blockDim.x >> 5)) ? red[lane] : 0.f;
        for (int off = 16; off > 0; off >>= 1) v += __shfl_xor_sync(0xffffffffu, v, off);
        if (lane == 0) red[0] = v;
    }
    __syncthreads();
    float scale = rsqrtf(red[0] / (float)DIM + 1e-5f);
    for (int i = threadIdx.x; i < DIM; i += blockDim.x)
        ob[i] = xb[i] * scale * w[i];
}

// ---------------- column-major GEMV (x[B,K] @ W[K,N]), float4 over N, k-split + atomics ----------------
__global__ void __launch_bounds__(128, 4)
gemv_cm4_kernel(const float* __restrict__ x, const float* __restrict__ W,
                float* __restrict__ out, int K, int N, int kchunk) {
    int n4 = blockIdx.x * blockDim.x + threadIdx.x;   // float4 column index
    int N4 = N >> 2;
    int k0 = blockIdx.y * kchunk;
    __shared__ float xs[B][128];
    float acc[4][B];
#pragma unroll
    for (int r = 0; r < 4; ++r)
#pragma unroll
        for (int b = 0; b < B; ++b) acc[r][b] = 0.f;
    const float4* W4 = (const float4*)W;
    for (int kb = k0; kb < k0 + kchunk; kb += 128) {
        __syncthreads();
        for (int i = threadIdx.x; i < B * 128; i += blockDim.x)
            xs[i >> 7][i & 127] = x[(size_t)(i >> 7) * K + kb + (i & 127)];
        __syncthreads();
#pragma unroll 8
        for (int kk = 0; kk < 128; ++kk) {
            float4 w = W4[(size_t)(kb + kk) * N4 + n4];
#pragma unroll
            for (int b = 0; b < B; ++b) {
                float xv = xs[b][kk];
                acc[0][b] += w.x * xv;
                acc[1][b] += w.y * xv;
                acc[2][b] += w.z * xv;
                acc[3][b] += w.w * xv;
            }
        }
    }
    int n = n4 * 4;
#pragma unroll
    for (int b = 0; b < B; ++b) {
#pragma unroll
        for (int r = 0; r < 4; ++r)
            atomicAdd(&out[(size_t)b * N + n + r], acc[r][b]);
    }
}

// ---------------- row-major GEMV, 4 rows per warp ----------------
__global__ void __launch_bounds__(256, 2)
gemv_rm4_kernel(const float* __restrict__ x, const float* __restrict__ W,
                float* __restrict__ out, int N, int K,
                const float* __restrict__ addsrc) {
    int warp = threadIdx.x >> 5, lane = threadIdx.x & 31;
    int n0 = (blockIdx.x * (blockDim.x >> 5) + warp) * 4;
    if (n0 >= N) return;
    int K4 = K >> 2;
    const float4* x4 = (const float4*)x;
    const float4* w0 = (const float4*)(W + (size_t)(n0 + 0) * K);
    const float4* w1 = (const float4*)(W + (size_t)(n0 + 1) * K);
    const float4* w2 = (const float4*)(W + (size_t)(n0 + 2) * K);
    const float4* w3 = (const float4*)(W + (size_t)(n0 + 3) * K);
    float acc[4][B];
#pragma unroll
    for (int r = 0; r < 4; ++r)
#pragma unroll
        for (int b = 0; b < B; ++b) acc[r][b] = 0.f;
#pragma unroll 2
    for (int i = lane; i < K4; i += 32) {
        float4 xv[B];
#pragma unroll
        for (int b = 0; b < B; ++b) xv[b] = x4[(size_t)b * K4 + i];
        float4 w;
        w = w0[i];
#pragma unroll
        for (int b = 0; b < B; ++b)
            acc[0][b] += w.x * xv[b].x + w.y * xv[b].y + w.z * xv[b].z + w.w * xv[b].w;
        w = w1[i];
#pragma unroll
        for (int b = 0; b < B; ++b)
            acc[1][b] += w.x * xv[b].x + w.y * xv[b].y + w.z * xv[b].z + w.w * xv[b].w;
        w = w2[i];
#pragma unroll
        for (int b = 0; b < B; ++b)
            acc[2][b] += w.x * xv[b].x + w.y * xv[b].y + w.z * xv[b].z + w.w * xv[b].w;
        w = w3[i];
#pragma unroll
        for (int b = 0; b < B; ++b)
            acc[3][b] += w.x * xv[b].x + w.y * xv[b].y + w.z * xv[b].z + w.w * xv[b].w;
    }
#pragma unroll
    for (int r = 0; r < 4; ++r)
#pragma unroll
        for (int b = 0; b < B; ++b)
#pragma unroll
            for (int off = 16; off > 0; off >>= 1)
                acc[r][b] += __shfl_xor_sync(0xffffffffu, acc[r][b], off);
    if (lane == 0) {
#pragma unroll
        for (int r = 0; r < 4; ++r) {
            int n = n0 + r;
            if (n < N) {
#pragma unroll
                for (int b = 0; b < B; ++b) {
                    float v = acc[r][b];
                    if (addsrc) v += addsrc[(size_t)b * N + n];
                    out[(size_t)b * N + n] = v;
                }
            }
        }
    }
}

// ---------------- rope + split qkv ----------------
__global__ void rope_split_kernel(const float* __restrict__ qkv,
                                  const float* __restrict__ fc, const float* __restrict__ fs,
                                  float* __restrict__ q, float* __restrict__ knew,
                                  float* __restrict__ vnew) {
    int b = blockIdx.x;
    const float* qb = qkv + (size_t)b * QKV_N;
    for (int i = threadIdx.x; i < NH * 64; i += blockDim.x) {
        int h = i >> 6, pi = i & 63;
        int g = h >> 3, r = h & 7;
        const float* base = qb + g * 1280 + r * 128;
        float re = base[2 * pi], im = base[2 * pi + 1];
        float c = fc[pi], s = fs[pi];
        float* qo = q + ((size_t)b * NH + h) * HEAD_DIM;
        qo[2 * pi] = re * c - im * s;
        qo[2 * pi + 1] = re * s + im * c;
    }
    for (int i = threadIdx.x; i < N_KV * 64; i += blockDim.x) {
        int g = i >> 6, pi = i & 63;
        const float* base = qb + g * 1280 + 1024;
        float re = base[2 * pi], im = base[2 * pi + 1];
        float c = fc[pi], s = fs[pi];
        float* ko = knew + ((size_t)b * N_KV + g) * HEAD_DIM;
        ko[2 * pi] = re * c - im * s;
        ko[2 * pi + 1] = re * s + im * c;
    }
    for (int i = threadIdx.x; i < N_KV * HEAD_DIM; i += blockDim.x) {
        int g = i >> 7, d = i & 127;
        vnew[((size_t)b * N_KV + g) * HEAD_DIM + d] = qb[g * 1280 + 1152 + d];
    }
}

// ---------------- scores: lane=(r, d-quarter), q in registers, K from global ----------------
__global__ void __launch_bounds__(256, 4)
scores3_kernel(const float* __restrict__ q, const float* __restrict__ cache_k,
               const float* __restrict__ knew, const float* __restrict__ mask,
               const int* __restrict__ sp_ptr, float* __restrict__ scores) {
    int b = blockIdx.z, g = blockIdx.y, j0 = blockIdx.x * 64;
    int sp = *sp_ptr;
    int warp = threadIdx.x >> 5, lane = threadIdx.x & 31;
    int r = lane & 7, dq = lane >> 3;   // 8 r's x 4 d-quarters
    __shared__ float sbuf[8 * 65];

    // q for this lane's (r, d-quarter): 8 float4 = 32 registers
    float4 q4[8];
    const float4* qbase = (const float4*)(q + ((size_t)b * NH + g * 8 + r) * HEAD_DIM);
#pragma unroll
    for (int it = 0; it < 8; ++it) q4[it] = qbase[dq * 8 + it];

    // each warp processes 8 j's
#pragma unroll
    for (int jj = 0; jj < 8; ++jj) {
        int jl = warp * 8 + jj;
        int j = j0 + jl;
        const float4* krow = (const float4*)((j == sp)
            ? (knew + ((size_t)b * N_KV + g) * HEAD_DIM)
            : (cache_k + (((size_t)b * KV + j) * N_KV + g) * HEAD_DIM));
        float acc = 0.f;
#pragma unroll
        for (int it = 0; it < 8; ++it) {
            float4 k4 = krow[dq * 8 + it];
            acc += k4.x * q4[it].x + k4.y * q4[it].y + k4.z * q4[it].z + k4.w * q4[it].w;
        }
        acc += __shfl_xor_sync(0xffffffffu, acc, 8);
        acc += __shfl_xor_sync(0xffffffffu, acc, 16);
        if (dq == 0) sbuf[r * 65 + jl] = acc;
    }
    __syncthreads();
    const float scale = 0.08838834764831845f;
    for (int idx = threadIdx.x; idx < 512; idx += 256) {
        int rr = idx >> 6, jl = idx & 63;
        int j = j0 + jl;
        scores[((size_t)b * NH + g * 8 + rr) * KV + j] = sbuf[rr * 65 + jl] * scale + mask[j];
    }
}

// ---------------- softmax over KV ----------------
__global__ void softmax_kernel(float* __restrict__ scores) {
    size_t row = blockIdx.x;
    float* p = scores + row * KV;
    __shared__ float red[32];
    int lane = threadIdx.x & 31, warp = threadIdx.x >> 5;
    float m = -1e30f;
    for (int i = threadIdx.x; i < KV; i += blockDim.x) m = fmaxf(m, p[i]);
    for (int off = 16; off > 0; off >>= 1) m = fmaxf(m, __shfl_xor_sync(0xffffffffu, m, off));
    if (lane == 0) red[warp] = m;
    __syncthreads();
    if (warp == 0) {
        float v = (lane < (int)(blockDim.x >> 5)) ? red[lane] : -1e30f;
        for (int off = 16; off > 0; off >>= 1) v = fmaxf(v, __shfl_xor_sync(0xffffffffu, v, off));
        if (lane == 0) red[0] = v;
    }
    __syncthreads();
    m = red[0];
    __syncthreads();
    float sum = 0.f;
    for (int i = threadIdx.x; i < KV; i += blockDim.x) {
        float e = expf(p[i] - m);
        p[i] = e;
        sum += e;
    }
    for (int off = 16; off > 0; off >>= 1) sum += __shfl_xor_sync(0xffffffffu, sum, off);
    if (lane == 0) red[warp] = sum;
    __syncthreads();
    if (warp == 0) {
        float v = (lane < (int)(blockDim.x >> 5)) ? red[lane] : 0.f;
        for (int off = 16; off > 0; off >>= 1) v += __shfl_xor_sync(0xffffffffu, v, off);
        if (lane == 0) red[0] = v;
    }
    __syncthreads();
    float inv = 1.f / red[0];
    for (int i = threadIdx.x; i < KV; i += blockDim.x) p[i] *= inv;
}

// ---------------- P@V: lane owns d (float4), no cross-lane reduce ----------------
__global__ void __launch_bounds__(256, 2)
pv3_kernel(const float* __restrict__ p, const float* __restrict__ cache_v,
           const float* __restrict__ vnew, const int* __restrict__ sp_ptr,
           float* __restrict__ attn_out) {
    int b = blockIdx.z, g = blockIdx.y, split = blockIdx.x;   // 4 splits of 1024 j
    int sp = *sp_ptr;
    int warp = threadIdx.x >> 5, lane = threadIdx.x & 31;
    int jstart = split * 1024;
    __shared__ float sbuf[8 * 1024];   // p stage, then reused for warp partials

    // stage p[8r][1024j]
    for (int i = threadIdx.x; i < 8 * 1024; i += 256) {
        int rr = i >> 10, jl = i & 1023;
        sbuf[i] = p[((size_t)b * NH + g * 8 + rr) * KV + jstart + jl];
    }
    __syncthreads();

    float4 acc[8];
#pragma unroll
    for (int rr = 0; rr < 8; ++rr) acc[rr] = make_float4(0.f, 0.f, 0.f, 0.f);

    // each warp: 128 j's
    for (int jj = 0; jj < 128; ++jj) {
        int jl = warp * 128 + jj;
        int j = jstart + jl;
        const float4* vrow = (const float4*)((j == sp)
            ? (vnew + ((size_t)b * N_KV + g) * HEAD_DIM)
            : (cache_v + (((size_t)b * KV + j) * N_KV + g) * HEAD_DIM));
        float4 v4 = vrow[lane];
#pragma unroll
        for (int rr = 0; rr < 8; ++rr) {
            float pr = sbuf[rr * 1024 + jl];
            acc[rr].x += pr * v4.x;
            acc[rr].y += pr * v4.y;
            acc[rr].z += pr * v4.z;
            acc[rr].w += pr * v4.w;
        }
    }
    __syncthreads();   // done reading p
    float4* wbuf = (float4*)sbuf;
#pragma unroll
    for (int rr = 0; rr < 8; ++rr) wbuf[((size_t)warp * 8 + rr) * 32 + lane] = acc[rr];
    __syncthreads();
    // reduce 8 warps -> atomics (256 outputs of float4)
    {
        int idx = threadIdx.x;
        int rr = idx >> 5, d4 = idx & 31;
        float4 s = make_float4(0.f, 0.f, 0.f, 0.f);
#pragma unroll
        for (int w = 0; w < 8; ++w) {
            float4 t = wbuf[((size_t)w * 8 + rr) * 32 + d4];
            s.x += t.x; s.y += t.y; s.z += t.z; s.w += t.w;
        }
        float* dst = attn_out + ((size_t)b * NH + g * 8 + rr) * HEAD_DIM + d4 * 4;
        atomicAdd(dst + 0, s.x);
        atomicAdd(dst + 1, s.y);
        atomicAdd(dst + 2, s.z);
        atomicAdd(dst + 3, s.w);
    }
}

// ---------------- gelu(t1)*t3 ----------------
__global__ void gelumul_kernel(const float* __restrict__ t1, const float* __restrict__ t3,
                               float* __restrict__ g, int n) {
    int i = blockIdx.x * blockDim.x + threadIdx.x;
    if (i < n) {
        float x = t1[i];
        g[i] = 0.5f * x * (1.f + erff(x * 0.7071067811865476f)) * t3[i];
    }
}

// ---------------- gate softmax + top-2 ----------------
__global__ void gate_topk_kernel(const float* __restrict__ logits, float* __restrict__ wexp) {
    int b = threadIdx.x;
    if (b >= B) return;
    float l[E];
    float m = -1e30f;
#pragma unroll
    for (int e = 0; e < E; ++e) { l[e] = logits[b * E + e]; m = fmaxf(m, l[e]); }
    float sum = 0.f;
#pragma unroll
    for (int e = 0; e < E; ++e) { l[e] = expf(l[e] - m); sum += l[e]; }
#pragma unroll
    for (int e = 0; e < E; ++e) l[e] /= sum;
    int i1 = 0;
#pragma unroll
    for (int e = 1; e < E; ++e) if (l[e] > l[i1]) i1 = e;
    int i2 = (i1 == 0) ? 1 : 0;
#pragma unroll
    for (int e = 0; e < E; ++e) if (e != i1 && l[e] > l[i2]) i2 = e;
#pragma unroll
    for (int e = 0; e < E; ++e)
        wexp[b * E + e] = (e == i1) ? l[i1] : (e == i2) ? l[i2] : 0.f;
}

// ---------------- MoE down-proj: 4 rows/warp, expert skip, weighted atomic accumulate ----------------
__global__ void __launch_bounds__(256, 2)
moe_second4_kernel(const float* __restrict__ ge, const float* __restrict__ w2,
                   const float* __restrict__ wexp, float* __restrict__ out) {
    int e = blockIdx.y;
    __shared__ float we[B];
    if (threadIdx.x < B) we[threadIdx.x] = wexp[threadIdx.x * E + e];
    __syncthreads();
    bool any = false;
#pragma unroll
    for (int b = 0; b < B; ++b) any |= (we[b] != 0.f);
    if (!any) return;

    int warp = threadIdx.x >> 5, lane = threadIdx.x & 31;
    int n0 = (blockIdx.x * 8 + warp) * 4;
    const float4* x4 = (const float4*)ge;
    int K4 = FE >> 2;
    const float4* w0 = (const float4*)(w2 + ((size_t)e * DIM + n0 + 0) * FE);
    const float4* w1 = (const float4*)(w2 + ((size_t)e * DIM + n0 + 1) * FE);
    const float4* w2p = (const float4*)(w2 + ((size_t)e * DIM + n0 + 2) * FE);
    const float4* w3 = (const float4*)(w2 + ((size_t)e * DIM + n0 + 3) * FE);
    float acc[4][B];
#pragma unroll
    for (int r = 0; r < 4; ++r)
#pragma unroll
        for (int b = 0; b < B; ++b) acc[r][b] = 0.f;
#pragma unroll 2
    for (int i = lane; i < K4; i += 32) {
        float4 xv[B];
#pragma unroll
        for (int b = 0; b < B; ++b) xv[b] = x4[((size_t)b * E + e) * K4 + i];
        float4 w;
        w = w0[i];
#pragma unroll
        for (int b = 0; b < B; ++b)
            acc[0][b] += w.x * xv[b].x + w.y * xv[b].y + w.z * xv[b].z + w.w * xv[b].w;
        w = w1[i];
#pragma unroll
        for (int b = 0; b < B; ++b)
            acc[1][b] += w.x * xv[b].x + w.y * xv[b].y + w.z * xv[b].z + w.w * xv[b].w;
        w = w2p[i];
#pragma unroll
        for (int b = 0; b < B; ++b)
            acc[2][b] += w.x * xv[b].x + w.y * xv[b].y + w.z * xv[b].z + w.w * xv[b].w;
        w = w3[i];
#pragma unroll
        for (int b = 0; b < B; ++b)
            acc[3][b] += w.x * xv[b].x + w.y * xv[b].y + w.z * xv[b].z + w.w * xv[b].w;
    }
#pragma unroll
    for (int r = 0; r < 4; ++r)
#pragma unroll
        for (int b = 0; b < B; ++b)
#pragma unroll
            for (int off = 16; off > 0; off >>= 1)
                acc[r][b] += __shfl_xor_sync(0xffffffffu, acc[r][b], off);
    if (lane == 0) {
#pragma unroll
        for (int r = 0; r < 4; ++r) {
            int n = n0 + r;
#pragma unroll
            for (int b = 0; b < B; ++b)
                if (we[b] != 0.f) atomicAdd(&out[(size_t)b * DIM + n], we[b] * acc[r][b]);
        }
    }
}

// ---------------- launch ----------------
extern "C" void kernel_launch(void* const* d_in, const int* in_sizes, int n_in,
                              void* d_out, int out_size) {
    const float* x        = (const float*)d_in[0];
    const float* mask     = (const float*)d_in[1];
    const float* fcos     = (const float*)d_in[2];
    const float* fsin     = (const float*)d_in[3];
    const float* cache_k  = (const float*)d_in[4];
    const float* cache_v  = (const float*)d_in[5];
    const float* wqkv     = (const float*)d_in[6];
    const float* wo       = (const float*)d_in[7];
    const float* attn_nw  = (const float*)d_in[8];
    const float* ffn_nw   = (const float*)d_in[9];
    const float* ffn_w1   = (const float*)d_in[10];
    const float* ffn_w2   = (const float*)d_in[11];
    const float* ffn_w3   = (const float*)d_in[12];
    const float* gate_w   = (const float*)d_in[13];
    const float* moe_w1   = (const float*)d_in[14];
    const float* moe_w2   = (const float*)d_in[15];
    const float* moe_w3   = (const float*)d_in[16];
    const int*   sp       = (const int*)d_in[17];
    float* out            = (float*)d_out;

    float *an, *qkv, *q, *knew, *vnew, *scores, *attn, *h, *fin, *t1, *t3, *gg;
    float *glog, *wexp, *h1, *h3, *ge;
    cudaGetSymbolAddress((void**)&an, g_an);
    cudaGetSymbolAddress((void**)&qkv, g_qkv);
    cudaGetSymbolAddress((void**)&q, g_q);
    cudaGetSymbolAddress((void**)&knew, g_knew);
    cudaGetSymbolAddress((void**)&vnew, g_vnew);
    cudaGetSymbolAddress((void**)&scores, g_scores);
    cudaGetSymbolAddress((void**)&attn, g_attn);
    cudaGetSymbolAddress((void**)&h, g_h);
    cudaGetSymbolAddress((void**)&fin, g_fin);
    cudaGetSymbolAddress((void**)&t1, g_t1);
    cudaGetSymbolAddress((void**)&t3, g_t3);
    cudaGetSymbolAddress((void**)&gg, g_g);
    cudaGetSymbolAddress((void**)&glog, g_glog);
    cudaGetSymbolAddress((void**)&wexp, g_wexp);
    cudaGetSymbolAddress((void**)&h1, g_h1);
    cudaGetSymbolAddress((void**)&h3, g_h3);
    cudaGetSymbolAddress((void**)&ge, g_ge);

    cudaMemsetAsync(qkv, 0, sizeof(float) * B * QKV_N);
    cudaMemsetAsync(attn, 0, sizeof(float) * B * DIM);

    // 1. attention pre-norm
    rmsnorm_kernel<<<B, 256>>>(x, attn_nw, an);
    // 2. qkv = an @ wqkv  (16 k-splits of 512)
    gemv_cm4_kernel<<<dim3((QKV_N / 4) / 128, 16), 128>>>(an, wqkv, qkv, DIM, QKV_N, DIM / 16);
    // 3. rope + split
    rope_split_kernel<<<B, 512>>>(qkv, fcos, fsin, q, knew, vnew);
    // 4. scores
    scores3_kernel<<<dim3(KV / 64, N_KV, B), 256>>>(q, cache_k, knew, mask, sp, scores);
    // 5. softmax
    softmax_kernel<<<B * NH, 256>>>(scores);
    // 6. P @ V
    pv3_kernel<<<dim3(4, N_KV, B), 256>>>(scores, cache_v, vnew, sp, attn);
    // 7. h = x + attn @ wo.T
    gemv_rm4_kernel<<<DIM / 32, 256>>>(attn, wo, h, DIM, DIM, x);
    // 8. ffn pre-norm
    rmsnorm_kernel<<<B, 256>>>(h, ffn_nw, fin);
    // 9. dense FFN
    gemv_rm4_kernel<<<FD / 32, 256>>>(fin, ffn_w1, t1, FD, DIM, nullptr);
    gemv_rm4_kernel<<<FD / 32, 256>>>(fin, ffn_w3, t3, FD, DIM, nullptr);
    gelumul_kernel<<<(B * FD) / 256, 256>>>(t1, t3, gg, B * FD);
    gemv_rm4_kernel<<<DIM / 32, 256>>>(gg, ffn_w2, out, DIM, FD, h);  // out = h + ff
    // 10. gating
    gemv_rm4_kernel<<<1, 256>>>(fin, gate_w, glog, E, DIM, nullptr);
    gate_topk_kernel<<<1, 32>>>(glog, wexp);
    // 11. MoE up-projections (dense over experts; moe_w1/w3 contiguous (E*FE, DIM))
    gemv_rm4_kernel<<<(E * FE) / 32, 256>>>(fin, moe_w1, h1, E * FE, DIM, nullptr);
    gemv_rm4_kernel<<<(E * FE) / 32, 256>>>(fin, moe_w3, h3, E * FE, DIM, nullptr);
    gelumul_kernel<<<(B * E * FE) / 256, 256>>>(h1, h3, ge, B * E * FE);
    // 12. MoE down-projection, weighted accumulate into out
    moe_second4_kernel<<<dim3(DIM / 32, E), 256>>>(ge, moe_w2, wexp, out);
}